// round 5
// baseline (speedup 1.0000x reference)
#include <cuda_runtime.h>

// ---------------- problem constants ----------------
#define NPTS   5000
#define DF     128
#define HF     208
#define WFE    208
#define HWSZ   (HF*WFE)        // 43264
#define LCC    10816
#define TPATCH 5
#define INV_S  0.08838834764831845f   // 1/sqrt(128)

// ---------------- device scratch (no allocations allowed) ----------------
__device__ float g_ctx0[2*DF];          // mean of feat_f0 per (b,c)
__device__ float g_ctx1[2*DF];          // mean of feat_f1 per (b,c)
__device__ float g_Wc[384*128];         // inv_s * corr_fuse_w @ M1
__device__ float g_Dc[256*128];         // down_proj_w @ M2
__device__ float g_biasc[128];          // corr_b@M1 + dp_b@M2 + merge_b
__device__ float g_Wbig[4*384*128];     // [half][b] combined 384x128 weights
__device__ float g_base[2*NPTS*128];    // per-(half,n) fc contribution + bias
__device__ int   g_glist[2*NPTS];       // n indices grouped by b
__device__ int   g_gcount[2];

// ---------------- f32x2 helpers ----------------
typedef unsigned long long ull;

__device__ __forceinline__ ull pk2(float a, float b) {
    ull r; asm("mov.b64 %0,{%1,%2};" : "=l"(r) : "f"(a), "f"(b)); return r;
}
__device__ __forceinline__ ull fma2(ull a, ull b, ull c) {
    ull d; asm("fma.rn.f32x2 %0,%1,%2,%3;" : "=l"(d) : "l"(a), "l"(b), "l"(c)); return d;
}
__device__ __forceinline__ float2 up2(ull v) {
    float2 r; asm("mov.b64 {%0,%1},%2;" : "=f"(r.x), "=f"(r.y) : "l"(v)); return r;
}

// ---------------- kernel 1: per-(b,c) spatial means ----------------
__global__ void ctx_kernel(const float* __restrict__ f0, const float* __restrict__ f1) {
    int id = blockIdx.x;                 // 0..511 : 0..255 -> f0, 256..511 -> f1
    const float* src = (id < 256) ? f0 : f1;
    int bc = id & 255;
    const float* p = src + (size_t)bc * HWSZ;
    float s = 0.f;
    for (int i = threadIdx.x; i < HWSZ; i += 256) s += p[i];
    __shared__ float red[256];
    red[threadIdx.x] = s;
    __syncthreads();
    for (int off = 128; off; off >>= 1) {
        if (threadIdx.x < off) red[threadIdx.x] += red[threadIdx.x + off];
        __syncthreads();
    }
    if (threadIdx.x == 0) {
        float m = red[0] * (1.0f / (float)HWSZ);
        if (id < 256) g_ctx0[bc] = m; else g_ctx1[bc] = m;
    }
}

// ---------------- kernel 2: fold merge weights into corr/down weights ----------------
// blocks 0..383: Wc rows;  384..639: Dc rows;  640: bias + zero group counters
__global__ void wcomb_kernel(const float* __restrict__ corr_w, const float* __restrict__ corr_b,
                             const float* __restrict__ dp_w,   const float* __restrict__ dp_b,
                             const float* __restrict__ mw,     const float* __restrict__ mb) {
    __shared__ float row[128];
    __shared__ float row2[128];
    int r = blockIdx.x;
    int c = threadIdx.x;
    if (r < 384) {
        row[c] = corr_w[r*128 + c];
        __syncthreads();
        float acc = 0.f;
        #pragma unroll 8
        for (int t = 0; t < 128; t++) acc += row[t] * mw[t*128 + c];
        g_Wc[r*128 + c] = acc * INV_S;
    } else if (r < 640) {
        int rr = r - 384;
        row[c] = dp_w[rr*128 + c];
        __syncthreads();
        float acc = 0.f;
        #pragma unroll 8
        for (int t = 0; t < 128; t++) acc += row[t] * mw[(128 + t)*128 + c];
        g_Dc[rr*128 + c] = acc;
    } else {
        row[c]  = corr_b[c];
        row2[c] = dp_b[c];
        __syncthreads();
        float acc = mb[c];
        #pragma unroll 4
        for (int t = 0; t < 128; t++)
            acc += row[t] * mw[t*128 + c] + row2[t] * mw[(128 + t)*128 + c];
        g_biasc[c] = acc;
        if (c == 0) { g_gcount[0] = 0; g_gcount[1] = 0; }
    }
}

// ---------------- kernel 3: build 4 combined 384x128 matrices ----------------
// panel layout in main GEMM: rows[0:128)->p0*p1, rows[128:256)->p0, rows[256:384)->p1
// half 0: p0 sect = ctx1[b] * Wc[128:256);  p1 sect = ctx0[b] * Wc[256:384)
// half 1: p0 sect = ctx1[b] * Wc[256:384);  p1 sect = ctx0[b] * Wc[128:256)
__global__ void wbig_kernel() {
    int r = blockIdx.x;
    int hb = blockIdx.y;
    int h = hb >> 1, b = hb & 1;
    int c = threadIdx.x;
    float s; int srcr;
    if (r < 128)      { s = 1.f;                     srcr = r; }
    else if (r < 256) { s = g_ctx1[b*128 + r - 128]; srcr = h ? (256 + (r - 128)) : r; }
    else              { s = g_ctx0[b*128 + r - 256]; srcr = h ? (128 + (r - 256)) : r; }
    g_Wbig[(size_t)(h*2 + b)*49152 + r*128 + c] = s * g_Wc[srcr*128 + c];
}

// ---------------- kernel 4: group points by b ----------------
__global__ void group_kernel(const int* __restrict__ b_ids) {
    int n = blockIdx.x * 256 + threadIdx.x;
    if (n < NPTS) {
        int g = b_ids[n];
        int p = atomicAdd(&g_gcount[g], 1);
        g_glist[g*NPTS + p] = n;
    }
}

// ---------------- kernel 5: base = fc @ Dc + biasc  (2N x 128) ----------------
// 32 rows per block -> 32KB static smem (must stay under the 48KB static limit)
__global__ __launch_bounds__(256) void base_kernel(
        const float* __restrict__ fc0, const float* __restrict__ fc1,
        const int* __restrict__ b_ids, const int* __restrict__ i_ids, const int* __restrict__ j_ids) {
    __shared__ float srcS[32*256];
    int tid = threadIdx.x;
    int row0 = blockIdx.x * 32;
    for (int it = tid; it < 32*64; it += 256) {          // 32 rows x 64 float4
        int rrow = it >> 6, ch = it & 63;
        int m = row0 + rrow;
        float4 v = make_float4(0.f, 0.f, 0.f, 0.f);
        if (m < 2*NPTS) {
            int half = (m >= NPTS);
            int n = m - half*NPTS;
            int b = b_ids[n];
            const float* src = half ? (fc1 + ((size_t)b*LCC + j_ids[n])*256)
                                    : (fc0 + ((size_t)b*LCC + i_ids[n])*256);
            v = __ldg((const float4*)src + ch);
        }
        *(float4*)(srcS + rrow*256 + ch*4) = v;
    }
    __syncthreads();
    int tx = tid & 31, ty = tid >> 5;                    // ty in [0,8): 4 rows each
    float acc[4][4];
    #pragma unroll
    for (int r = 0; r < 4; r++)
        #pragma unroll
        for (int c = 0; c < 4; c++) acc[r][c] = g_biasc[tx*4 + c];
    for (int k = 0; k < 256; k++) {
        float4 w = __ldg((const float4*)(g_Dc + k*128) + tx);
        #pragma unroll
        for (int r = 0; r < 4; r++) {
            float a = srcS[(ty*4 + r)*256 + k];
            acc[r][0] += a*w.x; acc[r][1] += a*w.y; acc[r][2] += a*w.z; acc[r][3] += a*w.w;
        }
    }
    #pragma unroll
    for (int r = 0; r < 4; r++) {
        int m = row0 + ty*4 + r;
        if (m < 2*NPTS)
            *(float4*)(g_base + (size_t)m*128 + tx*4) =
                make_float4(acc[r][0], acc[r][1], acc[r][2], acc[r][3]);
    }
}

// ---------------- kernel 6: main fused gather + (128x384)@(384x128) GEMM ----------------
// smem: p0s[5*25*128] | p1s[5*25*128] | cps[5*25*128] | Ws[32*128]  = 52096 floats = 208384 B
#define SMEM_FLOATS (3*TPATCH*25*128 + 32*128)

__global__ __launch_bounds__(256, 1) void main_kernel(
        const float* __restrict__ f0, const float* __restrict__ f1,
        const int* __restrict__ i_ids, const int* __restrict__ j_ids,
        const int* __restrict__ w0c_p, const int* __restrict__ w1c_p,
        float* __restrict__ out) {
    extern __shared__ float sm[];
    float* p0s = sm;
    float* p1s = sm + TPATCH*25*128;
    float* cps = sm + 2*TPATCH*25*128;
    float* Ws  = sm + 3*TPATCH*25*128;

    int group = blockIdx.y;              // == b
    int cnt = g_gcount[group];
    int tile = blockIdx.x;
    if (tile*TPATCH >= cnt) return;
    int tid = threadIdx.x;
    int w0c = *w0c_p, w1c = *w1c_p;

    int ns[TPATCH];
    int x0a[TPATCH], y0a[TPATCH], x1a[TPATCH], y1a[TPATCH];
    #pragma unroll
    for (int t = 0; t < TPATCH; t++) {
        int idx = tile*TPATCH + t;
        if (idx >= cnt) idx = cnt - 1;   // duplicate last -> identical redundant writes
        int n = g_glist[group*NPTS + idx];
        ns[t] = n;
        int ii = i_ids[n], jj = j_ids[n];
        int x0 = (ii % w0c)*2; if (x0 > WFE-1) x0 = WFE-1;
        int y0 = (ii / w0c)*2; if (y0 > HF -1) y0 = HF -1;
        int x1 = (jj % w1c)*2; if (x1 > WFE-1) x1 = WFE-1;
        int y1 = (jj / w1c)*2; if (y1 > HF -1) y1 = HF -1;
        x0a[t] = x0; y0a[t] = y0; x1a[t] = x1; y1a[t] = y1;
    }

    // ---- gather 5x5 patches, zero out-of-bounds ----
    #pragma unroll
    for (int t = 0; t < TPATCH; t++) {
        for (int item = tid; item < 640; item += 256) {    // item = c*5 + wy
            int wy = item % 5;
            int c  = item / 5;
            {
                int y = y0a[t] + wy - 2;
                bool yok = ((unsigned)y < (unsigned)HF);
                const float* src = f0 + ((size_t)(group*DF + c)*HF + (yok ? y : 0))*WFE;
                float* d = p0s + (t*25 + wy*5)*128 + c;
                #pragma unroll
                for (int wx = 0; wx < 5; wx++) {
                    int x = x0a[t] + wx - 2;
                    float v = (yok && (unsigned)x < (unsigned)WFE) ? __ldg(src + x) : 0.f;
                    d[wx*128] = v;
                }
            }
            {
                int y = y1a[t] + wy - 2;
                bool yok = ((unsigned)y < (unsigned)HF);
                const float* src = f1 + ((size_t)(group*DF + c)*HF + (yok ? y : 0))*WFE;
                float* d = p1s + (t*25 + wy*5)*128 + c;
                #pragma unroll
                for (int wx = 0; wx < 5; wx++) {
                    int x = x1a[t] + wx - 2;
                    float v = (yok && (unsigned)x < (unsigned)WFE) ? __ldg(src + x) : 0.f;
                    d[wx*128] = v;
                }
            }
        }
    }
    __syncthreads();
    for (int idx = tid; idx < TPATCH*25*128; idx += 256) cps[idx] = p0s[idx] * p1s[idx];

    // ---- per-thread tile meta: 8 rows (ty) x (cols tx*4..+3 and 64+tx*4..+3) ----
    int tx = tid & 15, ty = tid >> 4;
    int aoff[8], outn[8], outpos[8];
    bool rowok[8];
    #pragma unroll
    for (int r = 0; r < 8; r++) {
        int row = ty*8 + r;
        rowok[r] = (row < TPATCH*25);
        int rr = rowok[r] ? row : (TPATCH*25 - 1);
        int t = rr / 25, pos = rr % 25;
        aoff[r] = (t*25 + pos)*128;
        outn[r] = ns[t];
        outpos[r] = pos;
    }

    // prefetch half-0 panel 0
    float4 pf[4];
    {
        const float4* wsrc = (const float4*)(g_Wbig + (size_t)(0*2 + group)*49152);
        #pragma unroll
        for (int i = 0; i < 4; i++) pf[i] = __ldg(wsrc + i*256 + tid);
    }

    for (int half = 0; half < 2; half++) {
        const float* Wbase = g_Wbig + (size_t)(half*2 + group)*49152;
        ull acc[8][4];
        #pragma unroll
        for (int r = 0; r < 8; r++)
            #pragma unroll
            for (int p = 0; p < 4; p++) acc[r][p] = 0ull;

        #pragma unroll 1
        for (int panel = 0; panel < 12; panel++) {
            __syncthreads();
            #pragma unroll
            for (int i = 0; i < 4; i++) ((float4*)Ws)[i*256 + tid] = pf[i];
            // prefetch next panel (crossing into half 1's panel 0 at the seam)
            const float* nxt = (panel < 11) ? (Wbase + (panel + 1)*4096)
                              : ((half == 0) ? (g_Wbig + (size_t)(1*2 + group)*49152) : (const float*)0);
            if (nxt) {
                const float4* wsrc = (const float4*)nxt;
                #pragma unroll
                for (int i = 0; i < 4; i++) pf[i] = __ldg(wsrc + i*256 + tid);
            }
            __syncthreads();

            const float* Ab = (panel < 4) ? cps : ((panel < 8) ? p0s : p1s);
            int koff = (panel & 3)*32;
            #pragma unroll
            for (int k4 = 0; k4 < 8; k4++) {
                float av[8][4];
                #pragma unroll
                for (int r = 0; r < 8; r++) {
                    float4 tmp = *(const float4*)(Ab + aoff[r] + koff + k4*4);
                    av[r][0] = tmp.x; av[r][1] = tmp.y; av[r][2] = tmp.z; av[r][3] = tmp.w;
                }
                #pragma unroll
                for (int s = 0; s < 4; s++) {
                    int kk = k4*4 + s;
                    ulonglong2 bl0 = *(const ulonglong2*)(Ws + kk*128 + tx*4);
                    ulonglong2 bl1 = *(const ulonglong2*)(Ws + kk*128 + 64 + tx*4);
                    #pragma unroll
                    for (int r = 0; r < 8; r++) {
                        ull a2 = pk2(av[r][s], av[r][s]);
                        acc[r][0] = fma2(a2, bl0.x, acc[r][0]);
                        acc[r][1] = fma2(a2, bl0.y, acc[r][1]);
                        acc[r][2] = fma2(a2, bl1.x, acc[r][2]);
                        acc[r][3] = fma2(a2, bl1.y, acc[r][3]);
                    }
                }
            }
        }

        // ---- epilogue: add per-n base, write out ----
        #pragma unroll
        for (int r = 0; r < 8; r++) {
            if (!rowok[r]) continue;
            size_t mrow = (size_t)(half*NPTS + outn[r]);
            float4 bA = __ldg((const float4*)(g_base + mrow*128) + tx);
            float4 bB = __ldg((const float4*)(g_base + mrow*128 + 64) + tx);
            float2 u0 = up2(acc[r][0]), u1 = up2(acc[r][1]);
            float2 u2 = up2(acc[r][2]), u3 = up2(acc[r][3]);
            float4 vA = make_float4(u0.x + bA.x, u0.y + bA.y, u1.x + bA.z, u1.y + bA.w);
            float4 vB = make_float4(u2.x + bB.x, u2.y + bB.y, u3.x + bB.z, u3.y + bB.w);
            size_t orow = (mrow*25 + outpos[r])*128;
            *(float4*)(out + orow + tx*4) = vA;
            *(float4*)(out + orow + 64 + tx*4) = vB;
        }
    }
}

// ---------------- launch ----------------
extern "C" void kernel_launch(void* const* d_in, const int* in_sizes, int n_in,
                              void* d_out, int out_size) {
    const float* f0     = (const float*)d_in[0];
    const float* f1     = (const float*)d_in[1];
    const float* fc0    = (const float*)d_in[2];
    const float* fc1    = (const float*)d_in[3];
    const float* corr_w = (const float*)d_in[4];
    const float* corr_b = (const float*)d_in[5];
    const float* dp_w   = (const float*)d_in[6];
    const float* dp_b   = (const float*)d_in[7];
    const float* mw     = (const float*)d_in[8];
    const float* mb     = (const float*)d_in[9];
    const int* b_ids    = (const int*)d_in[10];
    const int* i_ids    = (const int*)d_in[11];
    const int* j_ids    = (const int*)d_in[12];
    const int* w0c      = (const int*)d_in[13];
    const int* w1c      = (const int*)d_in[14];
    float* out          = (float*)d_out;

    (void)in_sizes; (void)n_in; (void)out_size;

    cudaFuncSetAttribute(main_kernel, cudaFuncAttributeMaxDynamicSharedMemorySize,
                         SMEM_FLOATS * (int)sizeof(float));

    ctx_kernel  <<<512, 256>>>(f0, f1);
    wcomb_kernel<<<641, 128>>>(corr_w, corr_b, dp_w, dp_b, mw, mb);
    wbig_kernel <<<dim3(384, 4), 128>>>();
    group_kernel<<<(NPTS + 255)/256, 256>>>(b_ids);
    base_kernel <<<(2*NPTS + 31)/32, 256>>>(fc0, fc1, b_ids, i_ids, j_ids);
    main_kernel <<<dim3((NPTS + TPATCH - 1)/TPATCH, 2), 256,
                   SMEM_FLOATS * sizeof(float)>>>(f0, f1, i_ids, j_ids, w0c, w1c, out);
}

// round 13
// speedup vs baseline: 1.3192x; 1.3192x over previous
#include <cuda_runtime.h>
#include <cuda_bf16.h>
#include <cstdint>

// ---------------- problem constants ----------------
#define NPTS   5000
#define DF     128
#define HF     208
#define WFE    208
#define HWSZ   (HF*WFE)        // 43264
#define LCC    10816
#define TPATCH 5
#define INV_S  0.08838834764831845f   // 1/sqrt(128)

// ---------------- device scratch ----------------
__device__ float g_ctx0[2*DF];
__device__ float g_ctx1[2*DF];
__device__ float g_Wc[384*128];            // inv_s * corr_fuse_w @ M1
__device__ float g_Dc[256*128];            // down_proj_w @ M2
__device__ float g_biasc[128];
__device__ float g_Wbig[4*384*128];        // [half*2+b] combined 384x128 (row=k, col=n)
__device__ unsigned char g_WbigHL[4*12*16384]; // [hb][panel 0..11] bf16 hi/lo in mma-frag layout
__device__ float g_base[2*NPTS*128];
__device__ int   g_glist[2*NPTS];
__device__ int   g_gcount[2];

// ---------------- kernel 1: per-(b,c) spatial means ----------------
__global__ void ctx_kernel(const float* __restrict__ f0, const float* __restrict__ f1) {
    int id = blockIdx.x;
    const float* src = (id < 256) ? f0 : f1;
    int bc = id & 255;
    const float* p = src + (size_t)bc * HWSZ;
    float s = 0.f;
    for (int i = threadIdx.x; i < HWSZ; i += 256) s += p[i];
    __shared__ float red[256];
    red[threadIdx.x] = s;
    __syncthreads();
    for (int off = 128; off; off >>= 1) {
        if (threadIdx.x < off) red[threadIdx.x] += red[threadIdx.x + off];
        __syncthreads();
    }
    if (threadIdx.x == 0) {
        float m = red[0] * (1.0f / (float)HWSZ);
        if (id < 256) g_ctx0[bc] = m; else g_ctx1[bc] = m;
    }
}

// ---------------- kernel 2: fold merge weights ----------------
__global__ void wcomb_kernel(const float* __restrict__ corr_w, const float* __restrict__ corr_b,
                             const float* __restrict__ dp_w,   const float* __restrict__ dp_b,
                             const float* __restrict__ mw,     const float* __restrict__ mb) {
    __shared__ float row[128];
    __shared__ float row2[128];
    int r = blockIdx.x;
    int c = threadIdx.x;
    if (r < 384) {
        row[c] = corr_w[r*128 + c];
        __syncthreads();
        float acc = 0.f;
        #pragma unroll 8
        for (int t = 0; t < 128; t++) acc += row[t] * mw[t*128 + c];
        g_Wc[r*128 + c] = acc * INV_S;
    } else if (r < 640) {
        int rr = r - 384;
        row[c] = dp_w[rr*128 + c];
        __syncthreads();
        float acc = 0.f;
        #pragma unroll 8
        for (int t = 0; t < 128; t++) acc += row[t] * mw[(128 + t)*128 + c];
        g_Dc[rr*128 + c] = acc;
    } else {
        row[c]  = corr_b[c];
        row2[c] = dp_b[c];
        __syncthreads();
        float acc = mb[c];
        #pragma unroll 4
        for (int t = 0; t < 128; t++)
            acc += row[t] * mw[t*128 + c] + row2[t] * mw[(128 + t)*128 + c];
        g_biasc[c] = acc;
        if (c == 0) { g_gcount[0] = 0; g_gcount[1] = 0; }
    }
}

// ---------------- kernel 3: 4 combined 384x128 matrices ----------------
__global__ void wbig_kernel() {
    int r = blockIdx.x;
    int hb = blockIdx.y;
    int h = hb >> 1, b = hb & 1;
    int c = threadIdx.x;
    float s; int srcr;
    if (r < 128)      { s = 1.f;                     srcr = r; }
    else if (r < 256) { s = g_ctx1[b*128 + r - 128]; srcr = h ? (256 + (r - 128)) : r; }
    else              { s = g_ctx0[b*128 + r - 256]; srcr = h ? (128 + (r - 256)) : r; }
    g_Wbig[(size_t)(h*2 + b)*49152 + r*128 + c] = s * g_Wc[srcr*128 + c];
}

// ---------------- kernel 3b: B panels in mma-fragment layout ----------------
// panel pid<6: bh for k in [pid*64, pid*64+64); pid 6..11: bl for k in [(pid-6)*64, ...)
// Panel = 16KB: [kl(4 k16-steps)][ntile(16)][lane(32)][2 b32 regs]
// m16n8k16 B fragment: n = lane/4, k = (lane%4)*2 + (i&1) + (reg)*8
__global__ void whl_kernel() {
    int blk = blockIdx.x;              // hb*12 + pid
    int hb = blk / 12, pid = blk % 12;
    bool lo = (pid >= 6);
    int kbase = (lo ? pid - 6 : pid) * 64;
    const float* W = g_Wbig + (size_t)hb*49152;
    unsigned char* dst = g_WbigHL + (size_t)blk*16384;
    for (int e = threadIdx.x; e < 8192; e += 256) {
        int n = e >> 6, kloc = e & 63;
        float w = W[(size_t)(kbase + kloc)*128 + n];
        __nv_bfloat16 h = __float2bfloat16(w);
        __nv_bfloat16 v = lo ? __float2bfloat16(w - __bfloat162float(h)) : h;
        int kl = kloc >> 4, km = kloc & 15;
        int ntile = n >> 3, g = n & 7;
        int lane = g*4 + ((km & 7) >> 1);
        int reg  = km >> 3;
        int off = ((kl*16 + ntile)*32 + lane)*8 + reg*4 + (km & 1)*2;
        *(__nv_bfloat16*)(dst + off) = v;
    }
}

// ---------------- kernel 4: group points by b ----------------
__global__ void group_kernel(const int* __restrict__ b_ids) {
    int n = blockIdx.x * 256 + threadIdx.x;
    if (n < NPTS) {
        int g = b_ids[n];
        int p = atomicAdd(&g_gcount[g], 1);
        g_glist[g*NPTS + p] = n;
    }
}

// ---------------- kernel 5: base = fc @ Dc + biasc ----------------
__global__ __launch_bounds__(256) void base_kernel(
        const float* __restrict__ fc0, const float* __restrict__ fc1,
        const int* __restrict__ b_ids, const int* __restrict__ i_ids, const int* __restrict__ j_ids) {
    __shared__ float srcS[32*256];
    int tid = threadIdx.x;
    int row0 = blockIdx.x * 32;
    for (int it = tid; it < 32*64; it += 256) {
        int rrow = it >> 6, ch = it & 63;
        int m = row0 + rrow;
        float4 v = make_float4(0.f, 0.f, 0.f, 0.f);
        if (m < 2*NPTS) {
            int half = (m >= NPTS);
            int n = m - half*NPTS;
            int b = b_ids[n];
            const float* src = half ? (fc1 + ((size_t)b*LCC + j_ids[n])*256)
                                    : (fc0 + ((size_t)b*LCC + i_ids[n])*256);
            v = __ldg((const float4*)src + ch);
        }
        *(float4*)(srcS + rrow*256 + ch*4) = v;
    }
    __syncthreads();
    int tx = tid & 31, ty = tid >> 5;
    float acc[4][4];
    #pragma unroll
    for (int r = 0; r < 4; r++)
        #pragma unroll
        for (int c = 0; c < 4; c++) acc[r][c] = g_biasc[tx*4 + c];
    for (int k = 0; k < 256; k++) {
        float4 w = __ldg((const float4*)(g_Dc + k*128) + tx);
        #pragma unroll
        for (int r = 0; r < 4; r++) {
            float a = srcS[(ty*4 + r)*256 + k];
            acc[r][0] += a*w.x; acc[r][1] += a*w.y; acc[r][2] += a*w.z; acc[r][3] += a*w.w;
        }
    }
    #pragma unroll
    for (int r = 0; r < 4; r++) {
        int m = row0 + ty*4 + r;
        if (m < 2*NPTS)
            *(float4*)(g_base + (size_t)m*128 + tx*4) =
                make_float4(acc[r][0], acc[r][1], acc[r][2], acc[r][3]);
    }
}

// ---------------- kernel 6: gather + mma.sync bf16-split GEMM ----------------
// dynamic smem: A frag [0, 196608) ; B slot0 [196608, +16384) ; slot1 [212992, +16384)
#define SM_A_BYTES 196608
#define SM_B_OFF   196608
#define SMEM_BYTES 229376

// A fragment byte offset: [kstep(48)][mtile(8)][lane(32)][16B]
// m16n8k16 A frag: reg0:(row g, k tig*2+0/1) reg1:(g+8, same k) reg2:(g, k+8) reg3:(g+8, k+8)
__device__ __forceinline__ unsigned a_frag_off(int row, int k) {   // k in 0..767
    int kstep = k >> 4;
    int km = k & 15;
    int mtile = row >> 4;
    int lane = (row & 7)*4 + ((km & 7) >> 1);
    int reg  = ((km >> 3) << 1) | ((row >> 3) & 1);
    return (unsigned)((((kstep*8 + mtile)*32 + lane) << 4) + reg*4 + (km & 1)*2);
}
__device__ __forceinline__ void storeSplit(char* A, int row, int kc, float v) {
    __nv_bfloat16 h = __float2bfloat16(v);
    __nv_bfloat16 l = __float2bfloat16(v - __bfloat162float(h));
    *(__nv_bfloat16*)(A + a_frag_off(row, kc))       = h;
    *(__nv_bfloat16*)(A + a_frag_off(row, kc + 384)) = l;
}

__device__ __forceinline__ void mma_bf16(float* d, const uint4& a, const uint2& b) {
    asm volatile("mma.sync.aligned.m16n8k16.row.col.f32.bf16.bf16.f32 "
                 "{%0,%1,%2,%3}, {%4,%5,%6,%7}, {%8,%9}, {%0,%1,%2,%3};"
                 : "+f"(d[0]), "+f"(d[1]), "+f"(d[2]), "+f"(d[3])
                 : "r"(a.x), "r"(a.y), "r"(a.z), "r"(a.w), "r"(b.x), "r"(b.y));
}

__global__ __launch_bounds__(256, 1) void main_kernel(
        const float* __restrict__ f0, const float* __restrict__ f1,
        const int* __restrict__ i_ids, const int* __restrict__ j_ids,
        const int* __restrict__ w0c_p, const int* __restrict__ w1c_p,
        float* __restrict__ out) {
    extern __shared__ char smem[];
    int group = blockIdx.y;              // == b
    int cnt = g_gcount[group];
    int tile = blockIdx.x;
    if (tile*TPATCH >= cnt) return;

    int tid = threadIdx.x;
    int wid = tid >> 5;
    int lane = tid & 31;
    int wr = wid & 1, wc = wid >> 1;     // warp tile: m 64 x n 32
    int gl = lane >> 2, tig = lane & 3;  // fragment group / thread-in-group
    int w0c = *w0c_p, w1c = *w1c_p;

    // ---- zero-init the full A region (defines padded rows 125..127; no race:
    //      separated from the gather by a barrier) ----
    char* Abase = smem;
    {
        uint4 z = make_uint4(0u, 0u, 0u, 0u);
        #pragma unroll 4
        for (int zi = tid; zi < SM_A_BYTES/16; zi += 256) ((uint4*)Abase)[zi] = z;
    }
    __syncthreads();

    // ---- tile metadata ----
    int ns[TPATCH];
    int x0a[TPATCH], y0a[TPATCH], x1a[TPATCH], y1a[TPATCH];
    #pragma unroll
    for (int t = 0; t < TPATCH; t++) {
        int idx = tile*TPATCH + t;
        if (idx >= cnt) idx = cnt - 1;   // duplicate last -> identical redundant writes
        int n = g_glist[group*NPTS + idx];
        ns[t] = n;
        int ii = i_ids[n], jj = j_ids[n];
        int x0 = (ii % w0c)*2; if (x0 > WFE-1) x0 = WFE-1;
        int y0 = (ii / w0c)*2; if (y0 > HF -1) y0 = HF -1;
        int x1 = (jj % w1c)*2; if (x1 > WFE-1) x1 = WFE-1;
        int y1 = (jj / w1c)*2; if (y1 > HF -1) y1 = HF -1;
        x0a[t] = x0; y0a[t] = y0; x1a[t] = x1; y1a[t] = y1;
    }

    // ---- gather patches, bf16 hi/lo split into fragment-layout A ----
    #pragma unroll
    for (int t = 0; t < TPATCH; t++) {
        for (int item = tid; item < 640; item += 256) {    // item = c*5 + wy
            int wy = item % 5;
            int c  = item / 5;
            float v0[5], v1[5];
            {
                int y = y0a[t] + wy - 2;
                bool yok = ((unsigned)y < (unsigned)HF);
                const float* src = f0 + ((size_t)(group*DF + c)*HF + (yok ? y : 0))*WFE;
                #pragma unroll
                for (int wx = 0; wx < 5; wx++) {
                    int x = x0a[t] + wx - 2;
                    v0[wx] = (yok && (unsigned)x < (unsigned)WFE) ? __ldg(src + x) : 0.f;
                }
            }
            {
                int y = y1a[t] + wy - 2;
                bool yok = ((unsigned)y < (unsigned)HF);
                const float* src = f1 + ((size_t)(group*DF + c)*HF + (yok ? y : 0))*WFE;
                #pragma unroll
                for (int wx = 0; wx < 5; wx++) {
                    int x = x1a[t] + wx - 2;
                    v1[wx] = (yok && (unsigned)x < (unsigned)WFE) ? __ldg(src + x) : 0.f;
                }
            }
            #pragma unroll
            for (int wx = 0; wx < 5; wx++) {
                int row = t*25 + wy*5 + wx;
                storeSplit(Abase, row, c,        v0[wx]*v1[wx]);   // cps -> k 0..127
                storeSplit(Abase, row, 128 + c,  v0[wx]);          // p0  -> k 128..255
                storeSplit(Abase, row, 256 + c,  v1[wx]);          // p1  -> k 256..383
            }
        }
    }
    __syncthreads();

    // ---- streamed B + MMA ----
    float acc[4][4][4];
    #pragma unroll
    for (int i = 0; i < 4; i++)
        #pragma unroll
        for (int j = 0; j < 4; j++)
            #pragma unroll
            for (int q = 0; q < 4; q++) acc[i][j][q] = 0.f;

    uint4 pf[4];
    {
        const uint4* s0 = (const uint4*)(g_WbigHL + (size_t)((0*2 + group)*12 + 0)*16384);
        #pragma unroll
        for (int i = 0; i < 4; i++) pf[i] = __ldg(s0 + i*256 + tid);
    }

    #pragma unroll 1
    for (int gp = 0; gp < 36; gp++) {
        int half = gp / 18, Pl = gp % 18;
        int slot = gp & 1;
        char* Bslot = smem + SM_B_OFF + slot*16384;

        __syncthreads();                                   // slot free (readers of gp-2 done)
        #pragma unroll
        for (int i = 0; i < 4; i++) ((uint4*)Bslot)[i*256 + tid] = pf[i];
        // prefetch next panel
        if (gp + 1 < 36) {
            int g2 = gp + 1, h2 = g2 / 18, P2 = g2 % 18;
            int pid2 = (P2 < 12) ? P2 : P2 - 12;
            const uint4* s2 = (const uint4*)(g_WbigHL + (size_t)((h2*2 + group)*12 + pid2)*16384);
            #pragma unroll
            for (int i = 0; i < 4; i++) pf[i] = __ldg(s2 + i*256 + tid);
        }
        __syncthreads();                                   // slot filled

        #pragma unroll
        for (int kl = 0; kl < 4; kl++) {
            int c = Pl*4 + kl;                 // 0..71: ah*bh(0..23), ah*bl(24..47), al*bh(48..71)
            int a = (c < 24) ? c : c - 24;     // A kstep 0..47 (hi then lo)
            uint4 ua[4];
            #pragma unroll
            for (int mtl = 0; mtl < 4; mtl++)
                ua[mtl] = *(const uint4*)(Abase + (((a*8 + (wr*4 + mtl))*32 + lane) << 4));
            uint2 ub[4];
            #pragma unroll
            for (int ntl = 0; ntl < 4; ntl++)
                ub[ntl] = *(const uint2*)(Bslot + (((kl*16 + (wc*4 + ntl))*32 + lane) << 3));
            #pragma unroll
            for (int mtl = 0; mtl < 4; mtl++)
                #pragma unroll
                for (int ntl = 0; ntl < 4; ntl++)
                    mma_bf16(acc[mtl][ntl], ua[mtl], ub[ntl]);
        }

        // ---- end of a half: write out + reset acc ----
        if (Pl == 17) {
            #pragma unroll
            for (int mtl = 0; mtl < 4; mtl++) {
                #pragma unroll
                for (int rr = 0; rr < 2; rr++) {
                    int row = wr*64 + mtl*16 + gl + rr*8;
                    if (row < TPATCH*25) {
                        int t = row / 25, pos = row % 25;
                        size_t mrow = (size_t)half*NPTS + ns[t];
                        const float* bp = g_base + mrow*128;
                        float* op = out + (mrow*25 + pos)*128;
                        #pragma unroll
                        for (int ntl = 0; ntl < 4; ntl++) {
                            int col = wc*32 + ntl*8 + tig*2;
                            float2 b = *(const float2*)(bp + col);
                            float2 v;
                            v.x = acc[mtl][ntl][rr*2 + 0] + b.x;
                            v.y = acc[mtl][ntl][rr*2 + 1] + b.y;
                            *(float2*)(op + col) = v;
                        }
                    }
                }
            }
            #pragma unroll
            for (int i = 0; i < 4; i++)
                #pragma unroll
                for (int j = 0; j < 4; j++)
                    #pragma unroll
                    for (int q = 0; q < 4; q++) acc[i][j][q] = 0.f;
        }
    }
}

// ---------------- launch ----------------
extern "C" void kernel_launch(void* const* d_in, const int* in_sizes, int n_in,
                              void* d_out, int out_size) {
    const float* f0     = (const float*)d_in[0];
    const float* f1     = (const float*)d_in[1];
    const float* fc0    = (const float*)d_in[2];
    const float* fc1    = (const float*)d_in[3];
    const float* corr_w = (const float*)d_in[4];
    const float* corr_b = (const float*)d_in[5];
    const float* dp_w   = (const float*)d_in[6];
    const float* dp_b   = (const float*)d_in[7];
    const float* mw     = (const float*)d_in[8];
    const float* mb     = (const float*)d_in[9];
    const int* b_ids    = (const int*)d_in[10];
    const int* i_ids    = (const int*)d_in[11];
    const int* j_ids    = (const int*)d_in[12];
    const int* w0c      = (const int*)d_in[13];
    const int* w1c      = (const int*)d_in[14];
    float* out          = (float*)d_out;

    (void)in_sizes; (void)n_in; (void)out_size;

    cudaFuncSetAttribute(main_kernel, cudaFuncAttributeMaxDynamicSharedMemorySize, SMEM_BYTES);

    ctx_kernel  <<<512, 256>>>(f0, f1);
    wcomb_kernel<<<641, 128>>>(corr_w, corr_b, dp_w, dp_b, mw, mb);
    wbig_kernel <<<dim3(384, 4), 128>>>();
    whl_kernel  <<<48, 256>>>();
    group_kernel<<<(NPTS + 255)/256, 256>>>(b_ids);
    base_kernel <<<(2*NPTS + 31)/32, 256>>>(fc0, fc1, b_ids, i_ids, j_ids);
    main_kernel <<<dim3((NPTS + TPATCH - 1)/TPATCH, 2), 256, SMEM_BYTES>>>(
        f0, f1, i_ids, j_ids, w0c, w1c, out);
}

// round 14
// speedup vs baseline: 1.5658x; 1.1869x over previous
#include <cuda_runtime.h>
#include <cuda_bf16.h>
#include <cstdint>

// ---------------- problem constants ----------------
#define NPTS   5000
#define DF     128
#define HF     208
#define WFE    208
#define HWSZ   (HF*WFE)        // 43264
#define LCC    10816
#define TPATCH 5
#define INV_S  0.08838834764831845f   // 1/sqrt(128)

// ---------------- device scratch ----------------
__device__ float g_ctx0[2*DF];
__device__ float g_ctx1[2*DF];
__device__ float g_Wc[384*128];        // inv_s * corr_fuse_w @ M1
__device__ float g_Dc[256*128];        // down_proj_w @ M2
__device__ float g_biasc[128];
__device__ float g_Wtf[4*12*4096];     // [hb][panel 0..11] tf32 B panels in mma-frag layout
__device__ float g_base[2*NPTS*128];
__device__ int   g_glist[2*NPTS];
__device__ int   g_gcount[2];

__device__ __forceinline__ float to_tf32(float x) {
    unsigned u;
    asm("cvt.rna.tf32.f32 %0, %1;" : "=r"(u) : "f"(x));
    return __uint_as_float(u);
}

// ---------------- kernel 1: per-(b,c) spatial means ----------------
__global__ void ctx_kernel(const float* __restrict__ f0, const float* __restrict__ f1) {
    int id = blockIdx.x;
    const float* src = (id < 256) ? f0 : f1;
    int bc = id & 255;
    const float* p = src + (size_t)bc * HWSZ;
    float s = 0.f;
    for (int i = threadIdx.x; i < HWSZ; i += 256) s += p[i];
    __shared__ float red[256];
    red[threadIdx.x] = s;
    __syncthreads();
    for (int off = 128; off; off >>= 1) {
        if (threadIdx.x < off) red[threadIdx.x] += red[threadIdx.x + off];
        __syncthreads();
    }
    if (threadIdx.x == 0) {
        float m = red[0] * (1.0f / (float)HWSZ);
        if (id < 256) g_ctx0[bc] = m; else g_ctx1[bc] = m;
    }
}

// ---------------- kernel 2: fold merge weights ----------------
__global__ void wcomb_kernel(const float* __restrict__ corr_w, const float* __restrict__ corr_b,
                             const float* __restrict__ dp_w,   const float* __restrict__ dp_b,
                             const float* __restrict__ mw,     const float* __restrict__ mb) {
    __shared__ float row[128];
    __shared__ float row2[128];
    int r = blockIdx.x;
    int c = threadIdx.x;
    if (r < 384) {
        row[c] = corr_w[r*128 + c];
        __syncthreads();
        float acc = 0.f;
        #pragma unroll 8
        for (int t = 0; t < 128; t++) acc += row[t] * mw[t*128 + c];
        g_Wc[r*128 + c] = acc * INV_S;
    } else if (r < 640) {
        int rr = r - 384;
        row[c] = dp_w[rr*128 + c];
        __syncthreads();
        float acc = 0.f;
        #pragma unroll 8
        for (int t = 0; t < 128; t++) acc += row[t] * mw[(128 + t)*128 + c];
        g_Dc[rr*128 + c] = acc;
    } else {
        row[c]  = corr_b[c];
        row2[c] = dp_b[c];
        __syncthreads();
        float acc = mb[c];
        #pragma unroll 4
        for (int t = 0; t < 128; t++)
            acc += row[t] * mw[t*128 + c] + row2[t] * mw[(128 + t)*128 + c];
        g_biasc[c] = acc;
        if (c == 0) { g_gcount[0] = 0; g_gcount[1] = 0; }
    }
}

// ---------------- fused prep kernel ----------------
// blocks [0,48):   B panels: compute s*Wc on the fly, cvt to tf32, mma-frag layout
// blocks [48,68):  group points by b
// blocks [68,381): base = fc @ Dc + biasc
// B panel layout (16KB = 4096 f32): [q(4 k8-steps)][ntile(16)][lane(32)][2 regs]
// m16n8k8 B frag: b0:(k=tig, n=g) b1:(k=tig+4, n=g); lane = g*4 + tig
__global__ __launch_bounds__(256) void prep_kernel(
        const float* __restrict__ fc0, const float* __restrict__ fc1,
        const int* __restrict__ b_ids, const int* __restrict__ i_ids, const int* __restrict__ j_ids) {
    __shared__ float srcS[32*256];     // used by base part only
    int bx = blockIdx.x;
    int tid = threadIdx.x;

    if (bx < 48) {                     // ---- B panel build ----
        int hb = bx / 12, pid = bx % 12;
        int h = hb >> 1, b = hb & 1;
        float* dst = g_Wtf + (size_t)bx * 4096;
        for (int e = tid; e < 4096; e += 256) {
            int n = e >> 5;            // 0..127
            int kloc = e & 31;         // 0..31
            int k = pid*32 + kloc;     // global k 0..383
            float s; int srcr;
            if (k < 128)      { s = 1.f;                     srcr = k; }
            else if (k < 256) { s = g_ctx1[b*128 + k - 128]; srcr = h ? (k + 128) : k; }
            else              { s = g_ctx0[b*128 + k - 256]; srcr = h ? (k - 128) : k; }
            float w = s * g_Wc[srcr*128 + n];
            int q = kloc >> 3, kk = kloc & 7;
            int ntile = n >> 3, g = n & 7;
            int lane = g*4 + (kk & 3);
            int reg  = kk >> 2;
            dst[((q*16 + ntile)*32 + lane)*2 + reg] = to_tf32(w);
        }
        return;
    }
    if (bx < 68) {                     // ---- grouping ----
        int n = (bx - 48)*256 + tid;
        if (n < NPTS) {
            int g = b_ids[n];
            int p = atomicAdd(&g_gcount[g], 1);
            g_glist[g*NPTS + p] = n;
        }
        return;
    }
    // ---- base GEMM: rows [row0, row0+32) of 2N x 128 ----
    int row0 = (bx - 68) * 32;
    for (int it = tid; it < 32*64; it += 256) {
        int rrow = it >> 6, ch = it & 63;
        int m = row0 + rrow;
        float4 v = make_float4(0.f, 0.f, 0.f, 0.f);
        if (m < 2*NPTS) {
            int half = (m >= NPTS);
            int n = m - half*NPTS;
            int b = b_ids[n];
            const float* src = half ? (fc1 + ((size_t)b*LCC + j_ids[n])*256)
                                    : (fc0 + ((size_t)b*LCC + i_ids[n])*256);
            v = __ldg((const float4*)src + ch);
        }
        *(float4*)(srcS + rrow*256 + ch*4) = v;
    }
    __syncthreads();
    int tx = tid & 31, ty = tid >> 5;
    float acc[4][4];
    #pragma unroll
    for (int r = 0; r < 4; r++)
        #pragma unroll
        for (int c = 0; c < 4; c++) acc[r][c] = g_biasc[tx*4 + c];
    for (int k = 0; k < 256; k++) {
        float4 w = __ldg((const float4*)(g_Dc + k*128) + tx);
        #pragma unroll
        for (int r = 0; r < 4; r++) {
            float a = srcS[(ty*4 + r)*256 + k];
            acc[r][0] += a*w.x; acc[r][1] += a*w.y; acc[r][2] += a*w.z; acc[r][3] += a*w.w;
        }
    }
    #pragma unroll
    for (int r = 0; r < 4; r++) {
        int m = row0 + ty*4 + r;
        if (m < 2*NPTS)
            *(float4*)(g_base + (size_t)m*128 + tx*4) =
                make_float4(acc[r][0], acc[r][1], acc[r][2], acc[r][3]);
    }
}

// ---------------- main: gather + tf32 mma GEMM ----------------
// dynamic smem: A frag [0, 196608) ; B slot0 [196608, +16384) ; slot1 [212992, +16384)
#define SM_A_BYTES 196608
#define SM_B_OFF   196608
#define SMEM_BYTES 229376

// A fragment byte offset: [kstep(48)][mtile(8)][lane(32)][4 f32]
// m16n8k8 A frag: a0:(g, tig) a1:(g+8, tig) a2:(g, tig+4) a3:(g+8, tig+4)
__device__ __forceinline__ unsigned a_off(int row, int k) {   // k in 0..383
    int kstep = k >> 3, kk = k & 7;
    int mtile = row >> 4;
    int lane = (row & 7)*4 + (kk & 3);
    int reg  = ((kk >> 2) << 1) | ((row >> 3) & 1);
    return (unsigned)(((((kstep*8 + mtile)*32 + lane) << 2) + reg) << 2);
}
__device__ __forceinline__ void storeA(char* A, int row, int k, float v) {
    *(float*)(A + a_off(row, k)) = to_tf32(v);
}

__device__ __forceinline__ void mma_tf32(float* d, const uint4& a, const uint2& b) {
    asm volatile("mma.sync.aligned.m16n8k8.row.col.f32.tf32.tf32.f32 "
                 "{%0,%1,%2,%3}, {%4,%5,%6,%7}, {%8,%9}, {%0,%1,%2,%3};"
                 : "+f"(d[0]), "+f"(d[1]), "+f"(d[2]), "+f"(d[3])
                 : "r"(a.x), "r"(a.y), "r"(a.z), "r"(a.w), "r"(b.x), "r"(b.y));
}

__global__ __launch_bounds__(256, 1) void main_kernel(
        const float* __restrict__ f0, const float* __restrict__ f1,
        const int* __restrict__ i_ids, const int* __restrict__ j_ids,
        const int* __restrict__ w0c_p, const int* __restrict__ w1c_p,
        float* __restrict__ out) {
    extern __shared__ char smem[];
    int group = blockIdx.y;              // == b
    int cnt = g_gcount[group];
    int tile = blockIdx.x;
    if (tile*TPATCH >= cnt) return;

    int tid = threadIdx.x;
    int wid = tid >> 5;
    int lane = tid & 31;
    int wr = wid & 1, wc = wid >> 1;     // warp tile: m 64 x n 32
    int gl = lane >> 2, tig = lane & 3;  // fragment group / thread-in-group
    int w0c = *w0c_p, w1c = *w1c_p;

    // ---- zero-init A (defines padded rows 125..127) ----
    char* Abase = smem;
    {
        uint4 z = make_uint4(0u, 0u, 0u, 0u);
        #pragma unroll 4
        for (int zi = tid; zi < SM_A_BYTES/16; zi += 256) ((uint4*)Abase)[zi] = z;
    }
    __syncthreads();

    // ---- tile metadata ----
    int ns[TPATCH];
    int x0a[TPATCH], y0a[TPATCH], x1a[TPATCH], y1a[TPATCH];
    #pragma unroll
    for (int t = 0; t < TPATCH; t++) {
        int idx = tile*TPATCH + t;
        if (idx >= cnt) idx = cnt - 1;   // duplicate last -> identical redundant writes
        int n = g_glist[group*NPTS + idx];
        ns[t] = n;
        int ii = i_ids[n], jj = j_ids[n];
        int x0 = (ii % w0c)*2; if (x0 > WFE-1) x0 = WFE-1;
        int y0 = (ii / w0c)*2; if (y0 > HF -1) y0 = HF -1;
        int x1 = (jj % w1c)*2; if (x1 > WFE-1) x1 = WFE-1;
        int y1 = (jj / w1c)*2; if (y1 > HF -1) y1 = HF -1;
        x0a[t] = x0; y0a[t] = y0; x1a[t] = x1; y1a[t] = y1;
    }

    // ---- gather patches, tf32 round, into fragment-layout A ----
    #pragma unroll
    for (int t = 0; t < TPATCH; t++) {
        for (int item = tid; item < 640; item += 256) {    // item = c*5 + wy
            int wy = item % 5;
            int c  = item / 5;
            float v0[5], v1[5];
            {
                int y = y0a[t] + wy - 2;
                bool yok = ((unsigned)y < (unsigned)HF);
                const float* src = f0 + ((size_t)(group*DF + c)*HF + (yok ? y : 0))*WFE;
                #pragma unroll
                for (int wx = 0; wx < 5; wx++) {
                    int x = x0a[t] + wx - 2;
                    v0[wx] = (yok && (unsigned)x < (unsigned)WFE) ? __ldg(src + x) : 0.f;
                }
            }
            {
                int y = y1a[t] + wy - 2;
                bool yok = ((unsigned)y < (unsigned)HF);
                const float* src = f1 + ((size_t)(group*DF + c)*HF + (yok ? y : 0))*WFE;
                #pragma unroll
                for (int wx = 0; wx < 5; wx++) {
                    int x = x1a[t] + wx - 2;
                    v1[wx] = (yok && (unsigned)x < (unsigned)WFE) ? __ldg(src + x) : 0.f;
                }
            }
            #pragma unroll
            for (int wx = 0; wx < 5; wx++) {
                int row = t*25 + wy*5 + wx;
                storeA(Abase, row, c,        v0[wx]*v1[wx]);   // cps -> k 0..127
                storeA(Abase, row, 128 + c,  v0[wx]);          // p0  -> k 128..255
                storeA(Abase, row, 256 + c,  v1[wx]);          // p1  -> k 256..383
            }
        }
    }
    __syncthreads();

    // ---- streamed B + MMA: 24 panels (2 halves x 12) ----
    float acc[4][4][4];
    #pragma unroll
    for (int i = 0; i < 4; i++)
        #pragma unroll
        for (int j = 0; j < 4; j++)
            #pragma unroll
            for (int q = 0; q < 4; q++) acc[i][j][q] = 0.f;

    uint4 pf[4];
    {
        const uint4* s0 = (const uint4*)(g_Wtf + (size_t)((0*2 + group)*12 + 0)*4096);
        #pragma unroll
        for (int i = 0; i < 4; i++) pf[i] = __ldg(s0 + i*256 + tid);
    }

    #pragma unroll 1
    for (int gp = 0; gp < 24; gp++) {
        int half = gp / 12, Pl = gp % 12;
        int slot = gp & 1;
        char* Bslot = smem + SM_B_OFF + slot*16384;

        __syncthreads();                                   // slot free (readers of gp-2 done)
        #pragma unroll
        for (int i = 0; i < 4; i++) ((uint4*)Bslot)[i*256 + tid] = pf[i];
        // prefetch next panel
        if (gp + 1 < 24) {
            int g2 = gp + 1, h2 = g2 / 12, P2 = g2 % 12;
            const uint4* s2 = (const uint4*)(g_Wtf + (size_t)((h2*2 + group)*12 + P2)*4096);
            #pragma unroll
            for (int i = 0; i < 4; i++) pf[i] = __ldg(s2 + i*256 + tid);
        }
        __syncthreads();                                   // slot filled

        #pragma unroll
        for (int q = 0; q < 4; q++) {
            int kstep = Pl*4 + q;                          // A k8-step 0..47
            uint4 ua[4];
            #pragma unroll
            for (int mtl = 0; mtl < 4; mtl++)
                ua[mtl] = *(const uint4*)(Abase + (((kstep*8 + (wr*4 + mtl))*32 + lane) << 4));
            uint2 ub[4];
            #pragma unroll
            for (int ntl = 0; ntl < 4; ntl++)
                ub[ntl] = *(const uint2*)(Bslot + (((q*16 + (wc*4 + ntl))*32 + lane) << 3));
            #pragma unroll
            for (int mtl = 0; mtl < 4; mtl++)
                #pragma unroll
                for (int ntl = 0; ntl < 4; ntl++)
                    mma_tf32(acc[mtl][ntl], ua[mtl], ub[ntl]);
        }

        // ---- end of a half: write out + reset acc ----
        if (Pl == 11) {
            #pragma unroll
            for (int mtl = 0; mtl < 4; mtl++) {
                #pragma unroll
                for (int rr = 0; rr < 2; rr++) {
                    int row = wr*64 + mtl*16 + gl + rr*8;
                    if (row < TPATCH*25) {
                        int t = row / 25, pos = row % 25;
                        size_t mrow = (size_t)half*NPTS + ns[t];
                        const float* bp = g_base + mrow*128;
                        float* op = out + (mrow*25 + pos)*128;
                        #pragma unroll
                        for (int ntl = 0; ntl < 4; ntl++) {
                            int col = wc*32 + ntl*8 + tig*2;
                            float2 b = *(const float2*)(bp + col);
                            float2 v;
                            v.x = acc[mtl][ntl][rr*2 + 0] + b.x;
                            v.y = acc[mtl][ntl][rr*2 + 1] + b.y;
                            *(float2*)(op + col) = v;
                        }
                    }
                }
            }
            #pragma unroll
            for (int i = 0; i < 4; i++)
                #pragma unroll
                for (int j = 0; j < 4; j++)
                    #pragma unroll
                    for (int q = 0; q < 4; q++) acc[i][j][q] = 0.f;
        }
    }
}

// ---------------- launch ----------------
extern "C" void kernel_launch(void* const* d_in, const int* in_sizes, int n_in,
                              void* d_out, int out_size) {
    const float* f0     = (const float*)d_in[0];
    const float* f1     = (const float*)d_in[1];
    const float* fc0    = (const float*)d_in[2];
    const float* fc1    = (const float*)d_in[3];
    const float* corr_w = (const float*)d_in[4];
    const float* corr_b = (const float*)d_in[5];
    const float* dp_w   = (const float*)d_in[6];
    const float* dp_b   = (const float*)d_in[7];
    const float* mw     = (const float*)d_in[8];
    const float* mb     = (const float*)d_in[9];
    const int* b_ids    = (const int*)d_in[10];
    const int* i_ids    = (const int*)d_in[11];
    const int* j_ids    = (const int*)d_in[12];
    const int* w0c      = (const int*)d_in[13];
    const int* w1c      = (const int*)d_in[14];
    float* out          = (float*)d_out;

    (void)in_sizes; (void)n_in; (void)out_size;

    cudaFuncSetAttribute(main_kernel, cudaFuncAttributeMaxDynamicSharedMemorySize, SMEM_BYTES);

    ctx_kernel  <<<512, 256>>>(f0, f1);                    // launch 0
    wcomb_kernel<<<641, 128>>>(corr_w, corr_b, dp_w, dp_b, mw, mb);  // launch 1
    prep_kernel <<<381, 256>>>(fc0, fc1, b_ids, i_ids, j_ids);       // launch 2
    main_kernel <<<dim3((NPTS + TPATCH - 1)/TPATCH, 2), 256, SMEM_BYTES>>>(
        f0, f1, i_ids, j_ids, w0c, w1c, out);              // launch 3 -> ncu target
}